// round 1
// baseline (speedup 1.0000x reference)
#include <cuda_runtime.h>
#include <math.h>

#define NUM_HEADS 16
#define D_HEAD 64
#define BATCH 2
#define SEQ 2048
#define BH (BATCH*NUM_HEADS)   // 32

// Scratch (no cudaMalloc allowed): [B,H,S,d] fp32 each = 16 MB
__device__ float g_Q[BH*SEQ*D_HEAD];
__device__ float g_K[BH*SEQ*D_HEAD];
__device__ float g_V[BH*SEQ*D_HEAD];
__device__ float g_O[BH*SEQ*D_HEAD];

// ---------------------------------------------------------------------------
// Fused QKV projection: C[m,e] = sum_d x[m,d] * W[e,d]   (M=4096, N=1024 x3, K=1024)
// blockIdx.y: [0,48) -> which = y>>4 (0=Q,1=K,2=V), nt = y&15 (head index, BN=64==D_HEAD)
// Epilogue writes into [B,H,S,d] layout.
// ---------------------------------------------------------------------------
__global__ __launch_bounds__(256) void qkv_gemm(const float* __restrict__ x,
                                                const float* __restrict__ Wq,
                                                const float* __restrict__ Wk,
                                                const float* __restrict__ Wv) {
    int mt = blockIdx.x;
    int which = blockIdx.y >> 4;
    int nt = blockIdx.y & 15;
    const float* W = (which == 0) ? Wq : (which == 1) ? Wk : Wv;
    float* out = (which == 0) ? g_Q : (which == 1) ? g_K : g_V;

    __shared__ float As[16][68];   // [k][m]
    __shared__ float Bs[16][68];   // [k][n]

    int tid = threadIdx.x;
    int tx = tid & 15, ty = tid >> 4;
    int lm = tid >> 2;             // 0..63
    int lk = (tid & 3) * 4;        // 0,4,8,12

    const float* Ap = x + (size_t)(mt * 64 + lm) * 1024 + lk;
    const float* Bp = W + (size_t)(nt * 64 + lm) * 1024 + lk;

    float acc[4][4] = {};

    for (int k0 = 0; k0 < 1024; k0 += 16) {
        float4 a = *(const float4*)(Ap + k0);
        float4 b = *(const float4*)(Bp + k0);
        __syncthreads();
        As[lk + 0][lm] = a.x; As[lk + 1][lm] = a.y; As[lk + 2][lm] = a.z; As[lk + 3][lm] = a.w;
        Bs[lk + 0][lm] = b.x; Bs[lk + 1][lm] = b.y; Bs[lk + 2][lm] = b.z; Bs[lk + 3][lm] = b.w;
        __syncthreads();
#pragma unroll
        for (int kk = 0; kk < 16; kk++) {
            float4 av = *(const float4*)&As[kk][ty * 4];
            float4 bv = *(const float4*)&Bs[kk][tx * 4];
            float ar[4] = {av.x, av.y, av.z, av.w};
            float br[4] = {bv.x, bv.y, bv.z, bv.w};
#pragma unroll
            for (int r = 0; r < 4; r++)
#pragma unroll
                for (int c = 0; c < 4; c++)
                    acc[r][c] += ar[r] * br[c];
        }
    }

#pragma unroll
    for (int r = 0; r < 4; r++) {
        int m = mt * 64 + ty * 4 + r;
        int b = m >> 11, s = m & 2047;
        float4 o = make_float4(acc[r][0], acc[r][1], acc[r][2], acc[r][3]);
        *(float4*)(out + (((size_t)(b * 16 + nt) * SEQ + s) * 64 + tx * 4)) = o;
    }
}

// ---------------------------------------------------------------------------
// RoPE on Q and K in-place ([B,H,S,d] layout). One thread per even/odd pair.
// Double-precision angle for safety vs 1e-3 rel-err threshold.
// ---------------------------------------------------------------------------
__global__ void rope_kernel(const int* __restrict__ pos) {
    int t = blockIdx.x * blockDim.x + threadIdx.x;
    if (t >= BH * SEQ * 32) return;
    int p = t & 31;
    int s = (t >> 5) & 2047;
    double inv = exp(-(double)p * (9.210340371976184 / 32.0));  // 1/theta^(2p/64)
    double ang = (double)pos[s] * inv;
    double sn, cs;
    sincos(ang, &sn, &cs);
    float c = (float)cs, sf = (float)sn;

    float2 q = *(float2*)(g_Q + 2 * (size_t)t);
    float2 k = *(float2*)(g_K + 2 * (size_t)t);
    *(float2*)(g_Q + 2 * (size_t)t) = make_float2(q.x * c - q.y * sf, q.x * sf + q.y * c);
    *(float2*)(g_K + 2 * (size_t)t) = make_float2(k.x * c - k.y * sf, k.x * sf + k.y * c);
}

// ---------------------------------------------------------------------------
// Causal flash attention, fp32. One block per (q-tile of 64, head*batch).
// 256 threads as 16x16, 4x4 register tiles. Exactly 48KB static smem:
// P tile aliases the K buffer (K is reloaded every iteration).
// ---------------------------------------------------------------------------
__global__ __launch_bounds__(256) void flash_attn() {
    int qt = blockIdx.x;   // 0..31
    int bh = blockIdx.y;   // 0..31
    const float* Qp = g_Q + (size_t)bh * SEQ * 64;
    const float* Kp = g_K + (size_t)bh * SEQ * 64;
    const float* Vp = g_V + (size_t)bh * SEQ * 64;

    __shared__ float Qs[64][64];    // [d][m], pre-scaled by 1/8
    __shared__ float KPs[64][64];   // K as [d][n]; reused as P [j][i]
    __shared__ float Vs[64][64];    // [n][d]

    int tid = threadIdx.x;
    int tx = tid & 15, ty = tid >> 4;
    int ld_row = tid >> 4;           // 0..15
    int ld_d = (tid & 15) * 4;       // 0..60

#pragma unroll
    for (int pss = 0; pss < 4; pss++) {
        int row = pss * 16 + ld_row;
        float4 q = *(const float4*)(Qp + (size_t)(qt * 64 + row) * 64 + ld_d);
        Qs[ld_d + 0][row] = q.x * 0.125f;
        Qs[ld_d + 1][row] = q.y * 0.125f;
        Qs[ld_d + 2][row] = q.z * 0.125f;
        Qs[ld_d + 3][row] = q.w * 0.125f;
    }

    float acc[4][4] = {};
    float mrow[4] = {-INFINITY, -INFINITY, -INFINITY, -INFINITY};
    float lrow[4] = {};

    for (int kt = 0; kt <= qt; kt++) {
        __syncthreads();   // prior iter done reading P/V (and Q load done on iter 0)
#pragma unroll
        for (int pss = 0; pss < 4; pss++) {
            int row = pss * 16 + ld_row;
            float4 k = *(const float4*)(Kp + (size_t)(kt * 64 + row) * 64 + ld_d);
            KPs[ld_d + 0][row] = k.x;
            KPs[ld_d + 1][row] = k.y;
            KPs[ld_d + 2][row] = k.z;
            KPs[ld_d + 3][row] = k.w;
            float4 v = *(const float4*)(Vp + (size_t)(kt * 64 + row) * 64 + ld_d);
            *(float4*)&Vs[row][ld_d] = v;
        }
        __syncthreads();

        // S tile: s[r][c] = sum_d Q[i][d]*K[j][d], i=ty*4+r, j=tx*4+c
        float s[4][4] = {};
#pragma unroll
        for (int d = 0; d < 64; d++) {
            float4 qv = *(const float4*)&Qs[d][ty * 4];
            float4 kv = *(const float4*)&KPs[d][tx * 4];
            float qr[4] = {qv.x, qv.y, qv.z, qv.w};
            float kr[4] = {kv.x, kv.y, kv.z, kv.w};
#pragma unroll
            for (int r = 0; r < 4; r++)
#pragma unroll
                for (int c = 0; c < 4; c++)
                    s[r][c] += qr[r] * kr[c];
        }

        if (kt == qt) {
#pragma unroll
            for (int r = 0; r < 4; r++)
#pragma unroll
                for (int c = 0; c < 4; c++)
                    if (tx * 4 + c > ty * 4 + r) s[r][c] = -1e30f;
        }

        // Online softmax (rows shared by 16 consecutive lanes -> width-16 shuffles)
#pragma unroll
        for (int r = 0; r < 4; r++) {
            float mx = fmaxf(fmaxf(s[r][0], s[r][1]), fmaxf(s[r][2], s[r][3]));
#pragma unroll
            for (int off = 8; off >= 1; off >>= 1)
                mx = fmaxf(mx, __shfl_xor_sync(0xffffffffu, mx, off, 16));
            float mold = mrow[r];
            float mnew = fmaxf(mold, mx);
            float alpha = __expf(mold - mnew);
            mrow[r] = mnew;
            float sum = 0.f;
#pragma unroll
            for (int c = 0; c < 4; c++) {
                s[r][c] = __expf(s[r][c] - mnew);
                sum += s[r][c];
            }
#pragma unroll
            for (int off = 8; off >= 1; off >>= 1)
                sum += __shfl_xor_sync(0xffffffffu, sum, off, 16);
            lrow[r] = lrow[r] * alpha + sum;
#pragma unroll
            for (int c = 0; c < 4; c++) acc[r][c] *= alpha;
        }

        __syncthreads();   // everyone done reading K before P overwrites it
#pragma unroll
        for (int r = 0; r < 4; r++)
#pragma unroll
            for (int c = 0; c < 4; c++)
                KPs[tx * 4 + c][ty * 4 + r] = s[r][c];   // P transposed: [j][i]
        __syncthreads();

        // O += P @ V : acc[r][c] over (i=ty*4+r, dcol=tx*4+c)
#pragma unroll
        for (int j = 0; j < 64; j++) {
            float4 pv = *(const float4*)&KPs[j][ty * 4];
            float4 vv = *(const float4*)&Vs[j][tx * 4];
            float pr[4] = {pv.x, pv.y, pv.z, pv.w};
            float vr[4] = {vv.x, vv.y, vv.z, vv.w};
#pragma unroll
            for (int r = 0; r < 4; r++)
#pragma unroll
                for (int c = 0; c < 4; c++)
                    acc[r][c] += pr[r] * vr[c];
        }
    }

#pragma unroll
    for (int r = 0; r < 4; r++) {
        int row = qt * 64 + ty * 4 + r;
        float inv = 1.f / lrow[r];
        float4 o = make_float4(acc[r][0] * inv, acc[r][1] * inv, acc[r][2] * inv, acc[r][3] * inv);
        *(float4*)(g_O + ((size_t)bh * SEQ + row) * 64 + tx * 4) = o;
    }
}

// ---------------------------------------------------------------------------
// Output projection: C[m,e] = sum_k attn[m,k] * Wo[e,k], attn gathered from
// [B,H,S,d] layout (k = h*64 + j). Writes final [B,S,D_MODEL] output.
// ---------------------------------------------------------------------------
__global__ __launch_bounds__(256) void out_gemm(const float* __restrict__ Wo,
                                                float* __restrict__ out) {
    int mt = blockIdx.x;
    int nt = blockIdx.y;

    __shared__ float As[16][68];
    __shared__ float Bs[16][68];

    int tid = threadIdx.x;
    int tx = tid & 15, ty = tid >> 4;
    int lm = tid >> 2;
    int lk = (tid & 3) * 4;

    int m = mt * 64 + lm;
    int b = m >> 11, s = m & 2047;
    const float* Abase = g_O + ((size_t)b * 16 * SEQ + s) * 64;  // + h*SEQ*64 + j
    const float* Bp = Wo + (size_t)(nt * 64 + lm) * 1024 + lk;

    float acc[4][4] = {};

    for (int k0 = 0; k0 < 1024; k0 += 16) {
        int h = k0 >> 6;
        int j = (k0 & 63) + lk;
        float4 a = *(const float4*)(Abase + (size_t)h * SEQ * 64 + j);
        float4 bq = *(const float4*)(Bp + k0);
        __syncthreads();
        As[lk + 0][lm] = a.x; As[lk + 1][lm] = a.y; As[lk + 2][lm] = a.z; As[lk + 3][lm] = a.w;
        Bs[lk + 0][lm] = bq.x; Bs[lk + 1][lm] = bq.y; Bs[lk + 2][lm] = bq.z; Bs[lk + 3][lm] = bq.w;
        __syncthreads();
#pragma unroll
        for (int kk = 0; kk < 16; kk++) {
            float4 av = *(const float4*)&As[kk][ty * 4];
            float4 bv = *(const float4*)&Bs[kk][tx * 4];
            float ar[4] = {av.x, av.y, av.z, av.w};
            float br[4] = {bv.x, bv.y, bv.z, bv.w};
#pragma unroll
            for (int r = 0; r < 4; r++)
#pragma unroll
                for (int c = 0; c < 4; c++)
                    acc[r][c] += ar[r] * br[c];
        }
    }

#pragma unroll
    for (int r = 0; r < 4; r++) {
        int mrow = mt * 64 + ty * 4 + r;
        float4 o = make_float4(acc[r][0], acc[r][1], acc[r][2], acc[r][3]);
        *(float4*)(out + (size_t)mrow * 1024 + nt * 64 + tx * 4) = o;
    }
}

// ---------------------------------------------------------------------------
extern "C" void kernel_launch(void* const* d_in, const int* in_sizes, int n_in,
                              void* d_out, int out_size) {
    const float* x  = (const float*)d_in[0];
    const int*   tp = (const int*)d_in[1];
    const float* Wq = (const float*)d_in[2];
    const float* Wk = (const float*)d_in[3];
    const float* Wv = (const float*)d_in[4];
    const float* Wo = (const float*)d_in[5];
    float* out = (float*)d_out;

    qkv_gemm<<<dim3(64, 48), 256>>>(x, Wq, Wk, Wv);
    rope_kernel<<<(BH * SEQ * 32) / 256, 256>>>(tp);
    flash_attn<<<dim3(32, 32), 256>>>();
    out_gemm<<<dim3(64, 16), 256>>>(Wo, out);
}